// round 3
// baseline (speedup 1.0000x reference)
#include <cuda_runtime.h>

#define BATCH   128
#define NN      100
#define DD      128
#define ITILE   25          // i-rows per CTA  (100 / 25 = 4 tiles per batch)
#define NTILES  4
#define PITCH   132         // smem row pitch in floats: 132 % 32 == 4 -> conflict-free
#define THREADS 256
#define MASKV   (-9e15f)
#define NEG_BIG (-3.4e38f)

// dynamic smem layout (floats):
//   Hs : NN * PITCH            = 13200   (hidden[b], pitched)
//   At : 3  * PITCH            =   396   (A transposed, [k][d])
//   Bt : 9  * PITCH            =  1188   (Bm transposed, [k][d])
//   sA : ITILE * NN            =  2500   (scores / probs, relation A)
//   sB : ITILE * NN            =  2500   (scores / probs, relation B)
#define SMEM_FLOATS (NN*PITCH + 3*PITCH + 9*PITCH + 2*ITILE*NN)
#define SMEM_BYTES  (SMEM_FLOATS * 4)

extern "C" __global__ void __launch_bounds__(THREADS, 2)
la_kernel(const float* __restrict__ hidden,
          const int*   __restrict__ adj,
          const int*   __restrict__ beh,
          const float* __restrict__ A,
          const float* __restrict__ Bm,
          float*       __restrict__ out)
{
    extern __shared__ float smem[];
    float* Hs = smem;
    float* At = Hs + NN*PITCH;
    float* Bt = At + 3*PITCH;
    float* sA = Bt + 9*PITCH;
    float* sB = sA + ITILE*NN;

    const int tid = threadIdx.x;
    const int b   = blockIdx.x >> 2;            // NTILES == 4
    const int i0  = (blockIdx.x & 3) * ITILE;

    // ---- stage hidden[b] into pitched smem (float4) ----
    {
        const float4* hg = (const float4*)(hidden + (size_t)b * NN * DD);
        for (int v = tid; v < NN * (DD/4); v += THREADS) {
            int j = v >> 5;          // DD/4 == 32
            int q = v & 31;
            float4 x = hg[j * (DD/4) + q];
            *(float4*)&Hs[j * PITCH + q * 4] = x;
        }
    }
    // ---- stage A, Bm transposed: At[k][d] = A[d*3+k], Bt[k][d] = Bm[d*9+k] ----
    for (int t = tid; t < DD*3; t += THREADS) {
        int d = t / 3, k = t - d*3;
        At[k * PITCH + d] = A[t];
    }
    for (int t = tid; t < DD*9; t += THREADS) {
        int d = t / 9, k = t - d*9;
        Bt[k * PITCH + d] = Bm[t];
    }
    __syncthreads();

    // ---- score phase: gathered weighted dot per (i,j) pair ----
    const int* adjB = adj + (size_t)b * NN * NN;
    const int* behB = beh + (size_t)b * NN * NN;
    for (int p = tid; p < ITILE * NN; p += THREADS) {
        int il = p / NN;
        int j  = p - il * NN;
        int i  = i0 + il;
        int ca = adjB[i * NN + j];
        int cb = behB[i * NN + j];
        int ia = min(max(ca - 1, 0), 2);
        int ib = min(max(cb - 1, 0), 8);
        const float* hi = &Hs[i * PITCH];
        const float* hj = &Hs[j * PITCH];
        const float* ar = &At[ia * PITCH];
        const float* br = &Bt[ib * PITCH];
        float acc1 = 0.f, acc2 = 0.f;
        #pragma unroll 4
        for (int d = 0; d < DD; d += 4) {
            float4 x = *(const float4*)(hi + d);
            float4 y = *(const float4*)(hj + d);
            float4 a = *(const float4*)(ar + d);
            float4 w = *(const float4*)(br + d);
            float p0 = x.x * y.x, p1 = x.y * y.y, p2 = x.z * y.z, p3 = x.w * y.w;
            acc1 = fmaf(p0, a.x, acc1); acc1 = fmaf(p1, a.y, acc1);
            acc1 = fmaf(p2, a.z, acc1); acc1 = fmaf(p3, a.w, acc1);
            acc2 = fmaf(p0, w.x, acc2); acc2 = fmaf(p1, w.y, acc2);
            acc2 = fmaf(p2, w.z, acc2); acc2 = fmaf(p3, w.w, acc2);
        }
        // LeakyReLU(0.2) then relation-validity mask
        float e1 = acc1 >= 0.f ? acc1 : 0.2f * acc1;
        float e2 = acc2 >= 0.f ? acc2 : 0.2f * acc2;
        sA[p] = (ca >= 1 && ca <= 3) ? e1 : MASKV;
        sB[p] = (cb >= 1 && cb <= 9) ? e2 : MASKV;
    }
    __syncthreads();

    // ---- softmax over j, warp per row; fold GAMMA=0.5 into normalization ----
    {
        int w    = tid >> 5;
        int lane = tid & 31;
        for (int r = w; r < 2 * ITILE; r += THREADS / 32) {
            float* row = (r < ITILE) ? &sA[r * NN] : &sB[(r - ITILE) * NN];
            float v[4];
            float m = NEG_BIG;
            #pragma unroll
            for (int u = 0; u < 4; u++) {
                int j = lane + 32 * u;
                v[u] = (j < NN) ? row[j] : NEG_BIG;
                m = fmaxf(m, v[u]);
            }
            #pragma unroll
            for (int o = 16; o > 0; o >>= 1)
                m = fmaxf(m, __shfl_xor_sync(0xffffffffu, m, o));
            float s = 0.f;
            #pragma unroll
            for (int u = 0; u < 4; u++) {
                int j = lane + 32 * u;
                if (j < NN) { v[u] = __expf(v[u] - m); s += v[u]; }
            }
            #pragma unroll
            for (int o = 16; o > 0; o >>= 1)
                s += __shfl_xor_sync(0xffffffffu, s, o);
            float inv = 0.5f / s;   // GAMMA = 0.5 folded in here
            #pragma unroll
            for (int u = 0; u < 4; u++) {
                int j = lane + 32 * u;
                if (j < NN) row[j] = v[u] * inv;
            }
        }
    }
    __syncthreads();

    // ---- output: out[b, i0+il, :] = sum_j (pA+pB)[il][j] * h[b, j, :] ----
    {
        float* og = out + (size_t)b * NN * DD;
        for (int o = tid; o < ITILE * (DD/4); o += THREADS) {
            int il = o >> 5;                 // DD/4 == 32
            int d4 = (o & 31) * 4;
            const float* wa = &sA[il * NN];
            const float* wb = &sB[il * NN];
            float4 acc = make_float4(0.f, 0.f, 0.f, 0.f);
            #pragma unroll 4
            for (int j = 0; j < NN; j++) {
                float wt = wa[j] + wb[j];
                float4 hv = *(const float4*)&Hs[j * PITCH + d4];
                acc.x = fmaf(wt, hv.x, acc.x);
                acc.y = fmaf(wt, hv.y, acc.y);
                acc.z = fmaf(wt, hv.z, acc.z);
                acc.w = fmaf(wt, hv.w, acc.w);
            }
            *(float4*)&og[(i0 + il) * DD + d4] = acc;
        }
    }
}

extern "C" void kernel_launch(void* const* d_in, const int* in_sizes, int n_in,
                              void* d_out, int out_size)
{
    const float* hidden = (const float*)d_in[0];
    const int*   adj    = (const int*)  d_in[1];
    const int*   beh    = (const int*)  d_in[2];
    const float* A      = (const float*)d_in[3];
    const float* Bm     = (const float*)d_in[4];
    float*       out    = (float*)d_out;

    cudaFuncSetAttribute(la_kernel,
                         cudaFuncAttributeMaxDynamicSharedMemorySize,
                         SMEM_BYTES);

    dim3 grid(BATCH * NTILES);   // 512 CTAs
    la_kernel<<<grid, THREADS, SMEM_BYTES>>>(hidden, adj, beh, A, Bm, out);
}

// round 4
// speedup vs baseline: 1.2739x; 1.2739x over previous
#include <cuda_runtime.h>

#define BATCH   128
#define NN      100
#define DD      128
#define ITILE   20          // i-rows per CTA (100/20 = 5 tiles per batch)
#define NTILES  5
#define PITCH   132         // 132 % 32 == 4 -> conflict-free strided row reads
#define THREADS 128
#define MASKV   (-9e15f)
#define NEG_BIG (-3.4e38f)

// smem (floats): Hs 100*132 | At 3*132 | Bt 9*132 | sA 20*100 | sB 20*100
#define SMEM_FLOATS (NN*PITCH + 3*PITCH + 9*PITCH + 2*ITILE*NN)
#define SMEM_BYTES  (SMEM_FLOATS * 4)

extern "C" __global__ void __launch_bounds__(THREADS, 2)
la_kernel(const float* __restrict__ hidden,
          const int*   __restrict__ adj,
          const int*   __restrict__ beh,
          const float* __restrict__ A,
          const float* __restrict__ Bm,
          float*       __restrict__ out)
{
    extern __shared__ float smem[];
    float* Hs = smem;
    float* At = Hs + NN*PITCH;
    float* Bt = At + 3*PITCH;
    float* sA = Bt + 9*PITCH;
    float* sB = sA + ITILE*NN;

    const int tid = threadIdx.x;
    const int b   = blockIdx.x / NTILES;
    const int i0  = (blockIdx.x % NTILES) * ITILE;

    // ---- stage hidden[b] (pitched, float4) ----
    {
        const float4* hg = (const float4*)(hidden + (size_t)b * NN * DD);
        for (int v = tid; v < NN * (DD/4); v += THREADS) {
            int j = v >> 5;                       // DD/4 == 32
            int qq = v & 31;
            *(float4*)&Hs[j * PITCH + qq * 4] = hg[j * (DD/4) + qq];
        }
    }
    // ---- stage A,Bm transposed ----
    for (int t = tid; t < DD*3; t += THREADS) {
        int d = t / 3, k = t - d*3;
        At[k * PITCH + d] = A[t];
    }
    for (int t = tid; t < DD*9; t += THREADS) {
        int d = t / 9, k = t - d*9;
        Bt[k * PITCH + d] = Bm[t];
    }
    __syncthreads();

    // ---- score phase: 4i x 4j per thread, dense-A (3 ch) + gathered-B ----
    if (tid < 125) {
        const int p = tid / 25;                   // i-group 0..4
        const int q = tid - p * 25;               // j-group 0..24
        const int* adjB = adj + (size_t)b * NN * NN;
        const int* behB = beh + (size_t)b * NN * NN;

        unsigned iaPack = 0, vaPack = 0, vbPack = 0;
        const float* bp[4][4];
        #pragma unroll
        for (int t = 0; t < 4; t++) {
            int i = i0 + p + 5*t;
            #pragma unroll
            for (int s = 0; s < 4; s++) {
                int j  = q + 25*s;
                int ca = adjB[i * NN + j];
                int cb = behB[i * NN + j];
                int ia = min(max(ca - 1, 0), 2);
                int ib = min(max(cb - 1, 0), 8);
                int k  = t*4 + s;
                iaPack |= (unsigned)ia << (2*k);
                vaPack |= (unsigned)((ca >= 1) & (ca <= 3)) << k;
                vbPack |= (unsigned)(cb >= 1) << k;
                bp[t][s] = &Bt[ib * PITCH];
            }
        }
        const float* hiP[4]; const float* hjP[4];
        #pragma unroll
        for (int t = 0; t < 4; t++) hiP[t] = &Hs[(i0 + p + 5*t) * PITCH];
        #pragma unroll
        for (int s = 0; s < 4; s++) hjP[s] = &Hs[(q + 25*s) * PITCH];

        float a0c[4][4], a1c[4][4], a2c[4][4], bAc[4][4];
        #pragma unroll
        for (int t = 0; t < 4; t++)
            #pragma unroll
            for (int s = 0; s < 4; s++)
                a0c[t][s] = a1c[t][s] = a2c[t][s] = bAc[t][s] = 0.f;

        #pragma unroll 2
        for (int d = 0; d < DD; d += 4) {
            float4 w0 = *(const float4*)&At[d];               // broadcast
            float4 w1 = *(const float4*)&At[PITCH   + d];
            float4 w2 = *(const float4*)&At[2*PITCH + d];
            float4 hi[4], hj[4];
            #pragma unroll
            for (int t = 0; t < 4; t++) hi[t] = *(const float4*)(hiP[t] + d);
            #pragma unroll
            for (int s = 0; s < 4; s++) hj[s] = *(const float4*)(hjP[s] + d);
            #pragma unroll
            for (int t = 0; t < 4; t++) {
                #pragma unroll
                for (int s = 0; s < 4; s++) {
                    float4 bv = *(const float4*)(bp[t][s] + d); // gather
                    float p0 = hi[t].x * hj[s].x;
                    float p1 = hi[t].y * hj[s].y;
                    float p2 = hi[t].z * hj[s].z;
                    float p3 = hi[t].w * hj[s].w;
                    a0c[t][s] = fmaf(p0, w0.x, a0c[t][s]);
                    a0c[t][s] = fmaf(p1, w0.y, a0c[t][s]);
                    a0c[t][s] = fmaf(p2, w0.z, a0c[t][s]);
                    a0c[t][s] = fmaf(p3, w0.w, a0c[t][s]);
                    a1c[t][s] = fmaf(p0, w1.x, a1c[t][s]);
                    a1c[t][s] = fmaf(p1, w1.y, a1c[t][s]);
                    a1c[t][s] = fmaf(p2, w1.z, a1c[t][s]);
                    a1c[t][s] = fmaf(p3, w1.w, a1c[t][s]);
                    a2c[t][s] = fmaf(p0, w2.x, a2c[t][s]);
                    a2c[t][s] = fmaf(p1, w2.y, a2c[t][s]);
                    a2c[t][s] = fmaf(p2, w2.z, a2c[t][s]);
                    a2c[t][s] = fmaf(p3, w2.w, a2c[t][s]);
                    bAc[t][s] = fmaf(p0, bv.x, bAc[t][s]);
                    bAc[t][s] = fmaf(p1, bv.y, bAc[t][s]);
                    bAc[t][s] = fmaf(p2, bv.z, bAc[t][s]);
                    bAc[t][s] = fmaf(p3, bv.w, bAc[t][s]);
                }
            }
        }

        #pragma unroll
        for (int t = 0; t < 4; t++) {
            int il = p + 5*t;
            #pragma unroll
            for (int s = 0; s < 4; s++) {
                int j = q + 25*s;
                int k = t*4 + s;
                int ia = (iaPack >> (2*k)) & 3;
                float va = (ia == 0) ? a0c[t][s] : (ia == 1) ? a1c[t][s] : a2c[t][s];
                float vb = bAc[t][s];
                va = va >= 0.f ? va : 0.2f * va;       // LeakyReLU(0.2)
                vb = vb >= 0.f ? vb : 0.2f * vb;
                sA[il * NN + j] = ((vaPack >> k) & 1) ? va : MASKV;
                sB[il * NN + j] = ((vbPack >> k) & 1) ? vb : MASKV;
            }
        }
    }
    __syncthreads();

    // ---- dual softmax + combine: W[j] = 0.5*pA[j] + 0.5*pB[j] (into sA) ----
    {
        int w = tid >> 5, lane = tid & 31;
        for (int r = w; r < ITILE; r += THREADS/32) {
            float* rowA = &sA[r * NN];
            float* rowB = &sB[r * NN];
            float va[4], vb[4];
            float mA = NEG_BIG, mB = NEG_BIG;
            #pragma unroll
            for (int u = 0; u < 4; u++) {
                int j = lane + 32*u;
                va[u] = (j < NN) ? rowA[j] : NEG_BIG;
                vb[u] = (j < NN) ? rowB[j] : NEG_BIG;
                mA = fmaxf(mA, va[u]);
                mB = fmaxf(mB, vb[u]);
            }
            #pragma unroll
            for (int o = 16; o > 0; o >>= 1) {
                mA = fmaxf(mA, __shfl_xor_sync(0xffffffffu, mA, o));
                mB = fmaxf(mB, __shfl_xor_sync(0xffffffffu, mB, o));
            }
            float sAcc = 0.f, sBcc = 0.f;
            #pragma unroll
            for (int u = 0; u < 4; u++) {
                int j = lane + 32*u;
                if (j < NN) {
                    va[u] = __expf(va[u] - mA); sAcc += va[u];
                    vb[u] = __expf(vb[u] - mB); sBcc += vb[u];
                }
            }
            #pragma unroll
            for (int o = 16; o > 0; o >>= 1) {
                sAcc += __shfl_xor_sync(0xffffffffu, sAcc, o);
                sBcc += __shfl_xor_sync(0xffffffffu, sBcc, o);
            }
            float invA = 0.5f / sAcc;     // GAMMA folded
            float invB = 0.5f / sBcc;
            #pragma unroll
            for (int u = 0; u < 4; u++) {
                int j = lane + 32*u;
                if (j < NN) rowA[j] = va[u] * invA + vb[u] * invB;
            }
        }
    }
    __syncthreads();

    // ---- output: 2 i-rows per thread, W broadcast, hv read once ----
    {
        float* og = out + (size_t)b * NN * DD;
        for (int o = tid; o < (ITILE/2) * (DD/4); o += THREADS) {   // 320
            int il = o >> 5;                  // 0..9
            int d4 = (o & 31) * 4;
            const float* w1 = &sA[il * NN];
            const float* w2 = &sA[(il + 10) * NN];
            float4 acc1 = make_float4(0.f,0.f,0.f,0.f);
            float4 acc2 = make_float4(0.f,0.f,0.f,0.f);
            #pragma unroll 4
            for (int j = 0; j < NN; j++) {
                float t1 = w1[j];
                float t2 = w2[j];
                float4 hv = *(const float4*)&Hs[j * PITCH + d4];
                acc1.x = fmaf(t1, hv.x, acc1.x);
                acc1.y = fmaf(t1, hv.y, acc1.y);
                acc1.z = fmaf(t1, hv.z, acc1.z);
                acc1.w = fmaf(t1, hv.w, acc1.w);
                acc2.x = fmaf(t2, hv.x, acc2.x);
                acc2.y = fmaf(t2, hv.y, acc2.y);
                acc2.z = fmaf(t2, hv.z, acc2.z);
                acc2.w = fmaf(t2, hv.w, acc2.w);
            }
            *(float4*)&og[(i0 + il)      * DD + d4] = acc1;
            *(float4*)&og[(i0 + il + 10) * DD + d4] = acc2;
        }
    }
}

extern "C" void kernel_launch(void* const* d_in, const int* in_sizes, int n_in,
                              void* d_out, int out_size)
{
    const float* hidden = (const float*)d_in[0];
    const int*   adj    = (const int*)  d_in[1];
    const int*   beh    = (const int*)  d_in[2];
    const float* A      = (const float*)d_in[3];
    const float* Bm     = (const float*)d_in[4];
    float*       out    = (float*)d_out;

    cudaFuncSetAttribute(la_kernel,
                         cudaFuncAttributeMaxDynamicSharedMemorySize,
                         SMEM_BYTES);

    dim3 grid(BATCH * NTILES);    // 640 CTAs
    la_kernel<<<grid, THREADS, SMEM_BYTES>>>(hidden, adj, beh, A, Bm, out);
}

// round 6
// speedup vs baseline: 1.3991x; 1.0983x over previous
#include <cuda_runtime.h>

#define BATCH   128
#define NN      100
#define DD      128
#define ITILE   20          // i-rows per CTA (100/20 = 5 tiles per batch)
#define NTILES  5
#define PITCH   132         // 132 % 32 == 4 -> conflict-free strided row reads
#define THREADS 256
#define MASKV   (-9e15f)
#define NEG_BIG (-3.4e38f)

// smem (floats): Hs 100*132 | At 3*132 | Bt 9*132 | sA 20*100 | sB 20*100
#define SMEM_FLOATS (NN*PITCH + 3*PITCH + 9*PITCH + 2*ITILE*NN)
#define SMEM_BYTES  (SMEM_FLOATS * 4)

extern "C" __global__ void __launch_bounds__(THREADS, 2)
la_kernel(const float* __restrict__ hidden,
          const int*   __restrict__ adj,
          const int*   __restrict__ beh,
          const float* __restrict__ A,
          const float* __restrict__ Bm,
          float*       __restrict__ out)
{
    extern __shared__ float smem[];
    float* Hs = smem;
    float* At = Hs + NN*PITCH;
    float* Bt = At + 3*PITCH;
    float* sA = Bt + 9*PITCH;
    float* sB = sA + ITILE*NN;

    const int tid = threadIdx.x;
    const int b   = blockIdx.x / NTILES;
    const int i0  = (blockIdx.x % NTILES) * ITILE;

    // ---- stage hidden[b] (pitched, float4) ----
    {
        const float4* hg = (const float4*)(hidden + (size_t)b * NN * DD);
        for (int v = tid; v < NN * (DD/4); v += THREADS) {
            int j = v >> 5;                       // DD/4 == 32
            int qq = v & 31;
            *(float4*)&Hs[j * PITCH + qq * 4] = hg[j * (DD/4) + qq];
        }
    }
    // ---- stage A,Bm transposed ----
    for (int t = tid; t < DD*3; t += THREADS) {
        int d = t / 3, k = t - d*3;
        At[k * PITCH + d] = A[t];
    }
    for (int t = tid; t < DD*9; t += THREADS) {
        int d = t / 9, k = t - d*9;
        Bt[k * PITCH + d] = Bm[t];
    }
    __syncthreads();

    // ---- score phase: 2i x 4j per thread, dense-A (3 ch) + gathered-B ----
    if (tid < 250) {
        const int p = tid / 25;                   // i-group 0..9
        const int q = tid - p * 25;               // j-group 0..24
        const int* adjB = adj + (size_t)b * NN * NN;
        const int* behB = beh + (size_t)b * NN * NN;

        unsigned iaPack = 0, vaPack = 0, vbPack = 0;
        const float* bp[2][4];
        #pragma unroll
        for (int t = 0; t < 2; t++) {
            int i = i0 + p + 10*t;
            #pragma unroll
            for (int s = 0; s < 4; s++) {
                int j  = q + 25*s;
                int ca = adjB[i * NN + j];
                int cb = behB[i * NN + j];
                int ia = min(max(ca - 1, 0), 2);
                int ib = min(max(cb - 1, 0), 8);
                int k  = t*4 + s;
                iaPack |= (unsigned)ia << (2*k);
                vaPack |= (unsigned)((ca >= 1) & (ca <= 3)) << k;
                vbPack |= (unsigned)(cb >= 1) << k;
                bp[t][s] = &Bt[ib * PITCH];
            }
        }
        const float* hiP0 = &Hs[(i0 + p)      * PITCH];
        const float* hiP1 = &Hs[(i0 + p + 10) * PITCH];

        float a0c[2][4], a1c[2][4], a2c[2][4], bAc[2][4];
        #pragma unroll
        for (int t = 0; t < 2; t++)
            #pragma unroll
            for (int s = 0; s < 4; s++)
                a0c[t][s] = a1c[t][s] = a2c[t][s] = bAc[t][s] = 0.f;

        #pragma unroll 2
        for (int d = 0; d < DD; d += 4) {
            float4 w0 = *(const float4*)&At[d];               // broadcast
            float4 w1 = *(const float4*)&At[PITCH   + d];
            float4 w2 = *(const float4*)&At[2*PITCH + d];
            float4 hi[2], hj[4];
            hi[0] = *(const float4*)(hiP0 + d);
            hi[1] = *(const float4*)(hiP1 + d);
            #pragma unroll
            for (int s = 0; s < 4; s++)
                hj[s] = *(const float4*)&Hs[(q + 25*s) * PITCH + d];
            #pragma unroll
            for (int t = 0; t < 2; t++) {
                #pragma unroll
                for (int s = 0; s < 4; s++) {
                    float4 bv = *(const float4*)(bp[t][s] + d); // gather
                    float p0 = hi[t].x * hj[s].x;
                    float p1 = hi[t].y * hj[s].y;
                    float p2 = hi[t].z * hj[s].z;
                    float p3 = hi[t].w * hj[s].w;
                    a0c[t][s] = fmaf(p0, w0.x, a0c[t][s]);
                    a0c[t][s] = fmaf(p1, w0.y, a0c[t][s]);
                    a0c[t][s] = fmaf(p2, w0.z, a0c[t][s]);
                    a0c[t][s] = fmaf(p3, w0.w, a0c[t][s]);
                    a1c[t][s] = fmaf(p0, w1.x, a1c[t][s]);
                    a1c[t][s] = fmaf(p1, w1.y, a1c[t][s]);
                    a1c[t][s] = fmaf(p2, w1.z, a1c[t][s]);
                    a1c[t][s] = fmaf(p3, w1.w, a1c[t][s]);
                    a2c[t][s] = fmaf(p0, w2.x, a2c[t][s]);
                    a2c[t][s] = fmaf(p1, w2.y, a2c[t][s]);
                    a2c[t][s] = fmaf(p2, w2.z, a2c[t][s]);
                    a2c[t][s] = fmaf(p3, w2.w, a2c[t][s]);
                    bAc[t][s] = fmaf(p0, bv.x, bAc[t][s]);
                    bAc[t][s] = fmaf(p1, bv.y, bAc[t][s]);
                    bAc[t][s] = fmaf(p2, bv.z, bAc[t][s]);
                    bAc[t][s] = fmaf(p3, bv.w, bAc[t][s]);
                }
            }
        }

        #pragma unroll
        for (int t = 0; t < 2; t++) {
            int il = p + 10*t;
            #pragma unroll
            for (int s = 0; s < 4; s++) {
                int j = q + 25*s;
                int k = t*4 + s;
                int ia = (iaPack >> (2*k)) & 3;
                float va = (ia == 0) ? a0c[t][s] : (ia == 1) ? a1c[t][s] : a2c[t][s];
                float vb = bAc[t][s];
                va = va >= 0.f ? va : 0.2f * va;       // LeakyReLU(0.2)
                vb = vb >= 0.f ? vb : 0.2f * vb;
                sA[il * NN + j] = ((vaPack >> k) & 1) ? va : MASKV;
                sB[il * NN + j] = ((vbPack >> k) & 1) ? vb : MASKV;
            }
        }
    }
    __syncthreads();

    // ---- dual softmax + combine: W[j] = 0.5*pA[j] + 0.5*pB[j] (into sA) ----
    {
        int w = tid >> 5, lane = tid & 31;
        for (int r = w; r < ITILE; r += THREADS/32) {
            float* rowA = &sA[r * NN];
            float* rowB = &sB[r * NN];
            float va[4], vb[4];
            float mA = NEG_BIG, mB = NEG_BIG;
            #pragma unroll
            for (int u = 0; u < 4; u++) {
                int j = lane + 32*u;
                va[u] = (j < NN) ? rowA[j] : NEG_BIG;
                vb[u] = (j < NN) ? rowB[j] : NEG_BIG;
                mA = fmaxf(mA, va[u]);
                mB = fmaxf(mB, vb[u]);
            }
            #pragma unroll
            for (int o = 16; o > 0; o >>= 1) {
                mA = fmaxf(mA, __shfl_xor_sync(0xffffffffu, mA, o));
                mB = fmaxf(mB, __shfl_xor_sync(0xffffffffu, mB, o));
            }
            float sAcc = 0.f, sBcc = 0.f;
            #pragma unroll
            for (int u = 0; u < 4; u++) {
                int j = lane + 32*u;
                if (j < NN) {
                    va[u] = __expf(va[u] - mA); sAcc += va[u];
                    vb[u] = __expf(vb[u] - mB); sBcc += vb[u];
                }
            }
            #pragma unroll
            for (int o = 16; o > 0; o >>= 1) {
                sAcc += __shfl_xor_sync(0xffffffffu, sAcc, o);
                sBcc += __shfl_xor_sync(0xffffffffu, sBcc, o);
            }
            float invA = 0.5f / sAcc;     // GAMMA folded
            float invB = 0.5f / sBcc;
            #pragma unroll
            for (int u = 0; u < 4; u++) {
                int j = lane + 32*u;
                if (j < NN) rowA[j] = va[u] * invA + vb[u] * invB;
            }
        }
    }
    __syncthreads();

    // ---- output: 2 i-rows per thread, W broadcast, hv read once ----
    {
        float* og = out + (size_t)b * NN * DD;
        for (int o = tid; o < (ITILE/2) * (DD/4); o += THREADS) {   // 320
            int il = o >> 5;                  // 0..9
            int d4 = (o & 31) * 4;
            const float* w1 = &sA[il * NN];
            const float* w2 = &sA[(il + 10) * NN];
            float4 acc1 = make_float4(0.f,0.f,0.f,0.f);
            float4 acc2 = make_float4(0.f,0.f,0.f,0.f);
            #pragma unroll 4
            for (int j = 0; j < NN; j++) {
                float t1 = w1[j];
                float t2 = w2[j];
                float4 hv = *(const float4*)&Hs[j * PITCH + d4];
                acc1.x = fmaf(t1, hv.x, acc1.x);
                acc1.y = fmaf(t1, hv.y, acc1.y);
                acc1.z = fmaf(t1, hv.z, acc1.z);
                acc1.w = fmaf(t1, hv.w, acc1.w);
                acc2.x = fmaf(t2, hv.x, acc2.x);
                acc2.y = fmaf(t2, hv.y, acc2.y);
                acc2.z = fmaf(t2, hv.z, acc2.z);
                acc2.w = fmaf(t2, hv.w, acc2.w);
            }
            *(float4*)&og[(i0 + il)      * DD + d4] = acc1;
            *(float4*)&og[(i0 + il + 10) * DD + d4] = acc2;
        }
    }
}

extern "C" void kernel_launch(void* const* d_in, const int* in_sizes, int n_in,
                              void* d_out, int out_size)
{
    const float* hidden = (const float*)d_in[0];
    const int*   adj    = (const int*)  d_in[1];
    const int*   beh    = (const int*)  d_in[2];
    const float* A      = (const float*)d_in[3];
    const float* Bm     = (const float*)d_in[4];
    float*       out    = (float*)d_out;

    cudaFuncSetAttribute(la_kernel,
                         cudaFuncAttributeMaxDynamicSharedMemorySize,
                         SMEM_BYTES);

    dim3 grid(BATCH * NTILES);    // 640 CTAs
    la_kernel<<<grid, THREADS, SMEM_BYTES>>>(hidden, adj, beh, A, Bm, out);
}